// round 4
// baseline (speedup 1.0000x reference)
#include <cuda_runtime.h>
#include <cuda_bf16.h>
#include <math.h>

// ---------------------------------------------------------------------------
// 2-layer GCN:  h1 = relu(Agg(x@W1)+b1);  out = log_softmax(Agg(h1@W2)+b2)
// Agg: out[i] = sum_{e:(s->i)} dinv[s]*dinv[i]*h[s] + dinv[i]^2 * h[i]
// edge_index arrives as int32.
// GEMM1: warp-split-K, W1 in registers, packed fma.rn.f32x2, shfl-tree
// reduce, red.global partial accumulation into g_h1.
// ---------------------------------------------------------------------------

#define F_IN 512
#define HID  16
#define NCLS 2
#define NMAX 131072

typedef unsigned long long ull;

__device__ __align__(16) int   g_degcnt[NMAX];
__device__ __align__(16) float g_dinv[NMAX];
__device__ __align__(16) float g_h1[NMAX * HID];
__device__ __align__(16) float g_acc1[NMAX * HID];
__device__ __align__(16) float g_h2[NMAX * NCLS];
__device__ __align__(16) float g_acc2[NMAX * NCLS];

// ---------------- packed f32x2 helpers ----------------
__device__ __forceinline__ ull pk2(float lo, float hi) {
    ull r; asm("mov.b64 %0, {%1, %2};" : "=l"(r) : "f"(lo), "f"(hi)); return r;
}
__device__ __forceinline__ void pfma(ull& d, ull a, ull b) {
    asm("fma.rn.f32x2 %0, %1, %2, %0;" : "+l"(d) : "l"(a), "l"(b));
}
__device__ __forceinline__ ull padd(ull a, ull b) {
    ull r; asm("add.rn.f32x2 %0, %1, %2;" : "=l"(r) : "l"(a), "l"(b)); return r;
}
__device__ __forceinline__ float2 up2(ull v) {
    float2 f; asm("mov.b64 {%0, %1}, %2;" : "=f"(f.x), "=f"(f.y) : "l"(v)); return f;
}

// ---------------- vector reductions (sm_90+) ----------------
__device__ __forceinline__ void red_add_v4(float* p, float a, float b, float c, float d) {
    asm volatile("red.global.add.v4.f32 [%0], {%1,%2,%3,%4};"
                 :: "l"(p), "f"(a), "f"(b), "f"(c), "f"(d) : "memory");
}
__device__ __forceinline__ void red_add_v2(float* p, float a, float b) {
    asm volatile("red.global.add.v2.f32 [%0], {%1,%2};"
                 :: "l"(p), "f"(a), "f"(b) : "memory");
}

// ---------------- zero scratch ----------------
__global__ void k_zero(int N) {
    int i = blockIdx.x * blockDim.x + threadIdx.x;
    int n16 = N * HID;
    if (i < n16) { g_acc1[i] = 0.0f; g_h1[i] = 0.0f; }
    if (i < N) g_degcnt[i] = 0;
    if (i < N * NCLS) g_acc2[i] = 0.0f;
}

// ---------------- degree count ----------------
__global__ void k_deg(const int* __restrict__ dst, int E) {
    int e = blockIdx.x * blockDim.x + threadIdx.x;
    if (e >= E) return;
    atomicAdd(&g_degcnt[dst[e]], 1);
}

__global__ void k_dinv(int N) {
    int i = blockIdx.x * blockDim.x + threadIdx.x;
    if (i >= N) return;
    g_dinv[i] = rsqrtf((float)(g_degcnt[i] + 1));   // +1 self loop
}

// ---------------- GEMM1: h1 = x @ W1  (N x 512 @ 512 x 16) ----------------
// Block = 128 thr = 4 warps. Warp kq handles k in [kq*128, kq*128+128).
// Lane owns 4 consecutive k's; W1 slice (4x16) lives in 32 packed regs.
// Per row: 1 coalesced LDG.128 of x per lane, 32 pFMA, shfl halving tree,
// 8 lanes red.add.v2 the 16 partial columns into g_h1.
#define RPB 16

__global__ __launch_bounds__(128) void k_gemm1(const float* __restrict__ x,
                                               const float* __restrict__ W1, int N) {
    const int lane = threadIdx.x & 31;
    const int kq = threadIdx.x >> 5;
    const int row0 = blockIdx.x * RPB;
    const int kbase = kq * 128 + lane * 4;

    // W1 slice -> registers (once per block)
    ull Wr[4][8];
#pragma unroll
    for (int j = 0; j < 4; j++) {
        const float4* wp = (const float4*)(W1 + (size_t)(kbase + j) * HID);
#pragma unroll
        for (int q = 0; q < 4; q++) {
            float4 w = __ldg(wp + q);
            Wr[j][q * 2 + 0] = pk2(w.x, w.y);
            Wr[j][q * 2 + 1] = pk2(w.z, w.w);
        }
    }

    if (row0 >= N) return;
    int rend = row0 + RPB; if (rend > N) rend = N;

    float4 xv = *(const float4*)(x + (size_t)row0 * F_IN + kbase);

    for (int r = row0; r < rend; r++) {
        float4 xc = xv;
        if (r + 1 < rend)
            xv = *(const float4*)(x + (size_t)(r + 1) * F_IN + kbase);

        ull acc[8];
#pragma unroll
        for (int p = 0; p < 8; p++) acc[p] = 0ull;

#pragma unroll
        for (int j = 0; j < 4; j++) {
            float xk = (j == 0) ? xc.x : (j == 1) ? xc.y : (j == 2) ? xc.z : xc.w;
            ull xx = pk2(xk, xk);
#pragma unroll
            for (int p = 0; p < 8; p++) pfma(acc[p], xx, Wr[j][p]);
        }

        // halving butterfly: 8 pacc (16 cols) across 32 lanes
        if (lane & 16) {
#pragma unroll
            for (int j = 0; j < 4; j++) { ull t = acc[j]; acc[j] = acc[j + 4]; acc[j + 4] = t; }
        }
#pragma unroll
        for (int j = 0; j < 4; j++)
            acc[j] = padd(acc[j], __shfl_xor_sync(0xffffffffu, acc[j + 4], 16));

        if (lane & 8) { ull t0 = acc[0], t1 = acc[1]; acc[0] = acc[2]; acc[1] = acc[3]; acc[2] = t0; acc[3] = t1; }
#pragma unroll
        for (int j = 0; j < 2; j++)
            acc[j] = padd(acc[j], __shfl_xor_sync(0xffffffffu, acc[j + 2], 8));

        if (lane & 4) { ull t = acc[0]; acc[0] = acc[1]; acc[1] = t; }
        acc[0] = padd(acc[0], __shfl_xor_sync(0xffffffffu, acc[1], 4));
        acc[0] = padd(acc[0], __shfl_xor_sync(0xffffffffu, acc[0], 2));
        acc[0] = padd(acc[0], __shfl_xor_sync(0xffffffffu, acc[0], 1));

        if ((lane & 3) == 0) {
            int col = ((lane & 16) ? 8 : 0) | ((lane & 8) ? 4 : 0) | ((lane & 4) ? 2 : 0);
            float2 f = up2(acc[0]);
            red_add_v2(g_h1 + (size_t)r * HID + col, f.x, f.y);
        }
    }
}

// ---------------- scatter layer 1 (4 threads per edge) ----------------
__global__ void k_scatter1(const int* __restrict__ src,
                           const int* __restrict__ dst, int E) {
    int t = blockIdx.x * blockDim.x + threadIdx.x;
    if (t >= E * 4) return;
    int e = t >> 2, p = t & 3;
    int s = src[e];
    int d = dst[e];
    float nrm = g_dinv[s] * g_dinv[d];
    float4 h = *(const float4*)(g_h1 + (size_t)s * HID + p * 4);
    red_add_v4(g_acc1 + (size_t)d * HID + p * 4,
               h.x * nrm, h.y * nrm, h.z * nrm, h.w * nrm);
}

// ---------------- node: finish layer1 (self loop+bias+relu), h2 = t @ W2 ----
__global__ void k_node1(const float* __restrict__ b1, const float* __restrict__ W2, int N) {
    int i = blockIdx.x * blockDim.x + threadIdx.x;
    if (i >= N) return;
    float di = g_dinv[i];
    float d2 = di * di;
    float o0 = 0.f, o1 = 0.f;
#pragma unroll
    for (int q = 0; q < 4; q++) {
        float4 a = *(const float4*)(g_acc1 + (size_t)i * HID + q * 4);
        float4 h = *(const float4*)(g_h1 + (size_t)i * HID + q * 4);
        float4 bb = __ldg((const float4*)(b1 + q * 4));
        float t0 = fmaxf(a.x + d2 * h.x + bb.x, 0.f);
        float t1 = fmaxf(a.y + d2 * h.y + bb.y, 0.f);
        float t2 = fmaxf(a.z + d2 * h.z + bb.z, 0.f);
        float t3 = fmaxf(a.w + d2 * h.w + bb.w, 0.f);
        int c = q * 4;
        o0 = fmaf(t0, __ldg(W2 + (c + 0) * NCLS + 0), o0);
        o1 = fmaf(t0, __ldg(W2 + (c + 0) * NCLS + 1), o1);
        o0 = fmaf(t1, __ldg(W2 + (c + 1) * NCLS + 0), o0);
        o1 = fmaf(t1, __ldg(W2 + (c + 1) * NCLS + 1), o1);
        o0 = fmaf(t2, __ldg(W2 + (c + 2) * NCLS + 0), o0);
        o1 = fmaf(t2, __ldg(W2 + (c + 2) * NCLS + 1), o1);
        o0 = fmaf(t3, __ldg(W2 + (c + 3) * NCLS + 0), o0);
        o1 = fmaf(t3, __ldg(W2 + (c + 3) * NCLS + 1), o1);
    }
    g_h2[i * NCLS + 0] = o0;
    g_h2[i * NCLS + 1] = o1;
}

// ---------------- scatter layer 2 (1 thread per edge) ----------------
__global__ void k_scatter2(const int* __restrict__ src,
                           const int* __restrict__ dst, int E) {
    int e = blockIdx.x * blockDim.x + threadIdx.x;
    if (e >= E) return;
    int s = src[e];
    int d = dst[e];
    float nrm = g_dinv[s] * g_dinv[d];
    float h0 = g_h2[s * NCLS + 0];
    float h1v = g_h2[s * NCLS + 1];
    red_add_v2(g_acc2 + (size_t)d * NCLS, h0 * nrm, h1v * nrm);
}

// ---------------- final: self loop + bias + log_softmax ----------------
__global__ void k_out(const float* __restrict__ b2, float* __restrict__ out, int N) {
    int i = blockIdx.x * blockDim.x + threadIdx.x;
    if (i >= N) return;
    float di = g_dinv[i];
    float d2 = di * di;
    float v0 = g_acc2[i * NCLS + 0] + d2 * g_h2[i * NCLS + 0] + __ldg(b2 + 0);
    float v1 = g_acc2[i * NCLS + 1] + d2 * g_h2[i * NCLS + 1] + __ldg(b2 + 1);
    float m = fmaxf(v0, v1);
    float lse = m + logf(expf(v0 - m) + expf(v1 - m));
    out[i * NCLS + 0] = v0 - lse;
    out[i * NCLS + 1] = v1 - lse;
}

// ---------------------------------------------------------------------------
extern "C" void kernel_launch(void* const* d_in, const int* in_sizes, int n_in,
                              void* d_out, int out_size) {
    const float* x = (const float*)d_in[0];
    const int* ei = (const int*)d_in[1];
    const float* W1 = (const float*)d_in[2];
    const float* b1 = (const float*)d_in[3];
    const float* W2 = (const float*)d_in[4];
    const float* b2 = (const float*)d_in[5];
    float* out = (float*)d_out;

    const int N = in_sizes[0] / F_IN;
    const int E = in_sizes[1] / 2;
    const int* src = ei;
    const int* dst = ei + E;

    k_zero<<<(N * HID + 255) / 256, 256>>>(N);
    k_deg<<<(E + 255) / 256, 256>>>(dst, E);
    k_dinv<<<(N + 255) / 256, 256>>>(N);
    k_gemm1<<<(N + RPB - 1) / RPB, 128>>>(x, W1, N);
    k_scatter1<<<(E * 4 + 255) / 256, 256>>>(src, dst, E);
    k_node1<<<(N + 255) / 256, 256>>>(b1, W2, N);
    k_scatter2<<<(E + 255) / 256, 256>>>(src, dst, E);
    k_out<<<(N + 255) / 256, 256>>>(b2, out, N);
}

// round 5
// speedup vs baseline: 1.0774x; 1.0774x over previous
#include <cuda_runtime.h>
#include <cuda_bf16.h>
#include <math.h>

// ---------------------------------------------------------------------------
// 2-layer GCN via CSR-gather:
//   h1 = x @ W1                      (split-K f32x2 GEMM, red.v2 partials)
//   CSR build: deg -> scan -> fill   (edges bucketed by dst)
//   gather1: agg(h1) + self + b1, relu, @W2 -> h2   (warp per node)
//   gather2: agg(h2) + self + b2 -> log_softmax     (warp per node)
// edge_index arrives as int32.
// ---------------------------------------------------------------------------

#define F_IN 512
#define HID  16
#define NCLS 2
#define NMAX 131072
#define EMAX 3276800
#define SCAN_CH 2048   // elements per scan block (512 thr x 4)

typedef unsigned long long ull;

__device__ __align__(16) int   g_degcnt[NMAX];
__device__ __align__(16) int   g_incl[NMAX];
__device__ __align__(16) int   g_off[NMAX + 1];
__device__ __align__(16) int   g_cur[NMAX];
__device__ __align__(16) int   g_bsum[256];
__device__ __align__(16) int   g_boff[256];
__device__ __align__(16) float g_dinv[NMAX];
__device__ __align__(16) float g_h1[NMAX * HID];
__device__ __align__(16) float g_h2[NMAX * NCLS];
__device__ __align__(16) int   g_esrc[EMAX];

// ---------------- packed f32x2 helpers ----------------
__device__ __forceinline__ ull pk2(float lo, float hi) {
    ull r; asm("mov.b64 %0, {%1, %2};" : "=l"(r) : "f"(lo), "f"(hi)); return r;
}
__device__ __forceinline__ void pfma(ull& d, ull a, ull b) {
    asm("fma.rn.f32x2 %0, %1, %2, %0;" : "+l"(d) : "l"(a), "l"(b));
}
__device__ __forceinline__ ull padd(ull a, ull b) {
    ull r; asm("add.rn.f32x2 %0, %1, %2;" : "=l"(r) : "l"(a), "l"(b)); return r;
}
__device__ __forceinline__ float2 up2(ull v) {
    float2 f; asm("mov.b64 {%0, %1}, %2;" : "=f"(f.x), "=f"(f.y) : "l"(v)); return f;
}
__device__ __forceinline__ void red_add_v2(float* p, float a, float b) {
    asm volatile("red.global.add.v2.f32 [%0], {%1,%2};"
                 :: "l"(p), "f"(a), "f"(b) : "memory");
}

// ---------------- zero scratch (h1 partials + degree counters) ----------------
__global__ void k_zero(int N) {
    int i = blockIdx.x * blockDim.x + threadIdx.x;
    if (i < N * HID) g_h1[i] = 0.0f;
    if (i < N) g_degcnt[i] = 0;
}

// ---------------- degree count ----------------
__global__ void k_deg(const int* __restrict__ dst, int E) {
    int e = blockIdx.x * blockDim.x + threadIdx.x;
    if (e >= E) return;
    atomicAdd(&g_degcnt[dst[e]], 1);
}

// ---------------- scan pass 1: per-block inclusive scan + block sums ----------
__global__ __launch_bounds__(512) void k_scan1(int N) {
    __shared__ int wsum[16];
    const int t = threadIdx.x;
    const int base = blockIdx.x * SCAN_CH + t * 4;
    int v0 = (base + 0 < N) ? g_degcnt[base + 0] : 0;
    int v1 = (base + 1 < N) ? g_degcnt[base + 1] : 0;
    int v2 = (base + 2 < N) ? g_degcnt[base + 2] : 0;
    int v3 = (base + 3 < N) ? g_degcnt[base + 3] : 0;
    int s1 = v0 + v1, s2 = s1 + v2, s3 = s2 + v3;
    int tot = s3;

    int lane = t & 31, w = t >> 5;
    int sc = tot;
#pragma unroll
    for (int d = 1; d < 32; d <<= 1) {
        int u = __shfl_up_sync(0xffffffffu, sc, d);
        if (lane >= d) sc += u;
    }
    if (lane == 31) wsum[w] = sc;
    __syncthreads();
    if (w == 0) {
        int x = (lane < 16) ? wsum[lane] : 0;
#pragma unroll
        for (int d = 1; d < 16; d <<= 1) {
            int u = __shfl_up_sync(0xffffffffu, x, d);
            if (lane >= d) x += u;
        }
        if (lane < 16) wsum[lane] = x;
    }
    __syncthreads();
    int woff = (w > 0) ? wsum[w - 1] : 0;
    int excl = woff + sc - tot;
    if (base + 0 < N) g_incl[base + 0] = excl + v0;
    if (base + 1 < N) g_incl[base + 1] = excl + s1;
    if (base + 2 < N) g_incl[base + 2] = excl + s2;
    if (base + 3 < N) g_incl[base + 3] = excl + s3;
    if (t == 0) g_bsum[blockIdx.x] = wsum[15];
}

// ---------------- scan pass 2: exclusive scan of block sums (<=256 blocks) ----
__global__ void k_scan2(int NB) {
    __shared__ int sm[256];
    int t = threadIdx.x;            // 256 threads
    sm[t] = (t < NB) ? g_bsum[t] : 0;
    __syncthreads();
    if (t == 0) {                    // serial in smem: NB<=64 in practice
        int run = 0;
        for (int b = 0; b < NB; b++) { int v = sm[b]; sm[b] = run; run += v; }
    }
    __syncthreads();
    if (t < NB) g_boff[t] = sm[t];
}

// ---------------- scan pass 3: offsets, cursors, dinv ----------------
__global__ void k_scan3(int N, int E) {
    int i = blockIdx.x * blockDim.x + threadIdx.x;
    if (i >= N) return;
    int deg = g_degcnt[i];
    int off = g_boff[i / SCAN_CH] + g_incl[i] - deg;
    g_off[i] = off;
    g_cur[i] = off;
    g_dinv[i] = rsqrtf((float)(deg + 1));     // +1 self loop
    if (i == 0) g_off[N] = E;
}

// ---------------- fill CSR edge list ----------------
__global__ void k_fill(const int* __restrict__ src,
                       const int* __restrict__ dst, int E) {
    int e = blockIdx.x * blockDim.x + threadIdx.x;
    if (e >= E) return;
    int d = dst[e];
    int slot = atomicAdd(&g_cur[d], 1);
    g_esrc[slot] = src[e];
}

// ---------------- GEMM1: h1 = x @ W1  (N x 512 @ 512 x 16) ----------------
// Block = 128 thr = 4 warps; warp kq owns k in [kq*128, kq*128+128); lane owns
// 4 consecutive k (W slice in 32 packed regs). 2-row batches, double-buffered
// loads (2 LDG.128/lane in flight), interleaved butterflies, red.add.v2 out.
#define RPB 16

__global__ __launch_bounds__(128) void k_gemm1(const float* __restrict__ x,
                                               const float* __restrict__ W1, int N) {
    const int lane = threadIdx.x & 31;
    const int kq = threadIdx.x >> 5;
    const int row0 = blockIdx.x * RPB;
    const int kbase = kq * 128 + lane * 4;

    ull Wr[4][8];
#pragma unroll
    for (int j = 0; j < 4; j++) {
        const float4* wp = (const float4*)(W1 + (size_t)(kbase + j) * HID);
#pragma unroll
        for (int q = 0; q < 4; q++) {
            float4 w = __ldg(wp + q);
            Wr[j][q * 2 + 0] = pk2(w.x, w.y);
            Wr[j][q * 2 + 1] = pk2(w.z, w.w);
        }
    }

    if (row0 >= N) return;
    int rend = row0 + RPB; if (rend > N) rend = N;

    float4 xa = *(const float4*)(x + (size_t)row0 * F_IN + kbase);
    float4 xb = (row0 + 1 < rend) ? *(const float4*)(x + (size_t)(row0 + 1) * F_IN + kbase)
                                  : xa;

    for (int r = row0; r < rend; r += 2) {
        float4 xc[2]; xc[0] = xa; xc[1] = xb;
        if (r + 2 < rend) {
            xa = *(const float4*)(x + (size_t)(r + 2) * F_IN + kbase);
            if (r + 3 < rend)
                xb = *(const float4*)(x + (size_t)(r + 3) * F_IN + kbase);
        }
        const bool two = (r + 1 < rend);

        ull acc[2][8];
#pragma unroll
        for (int rr = 0; rr < 2; rr++)
#pragma unroll
            for (int p = 0; p < 8; p++) acc[rr][p] = 0ull;

#pragma unroll
        for (int j = 0; j < 4; j++) {
#pragma unroll
            for (int rr = 0; rr < 2; rr++) {
                float xk = (j == 0) ? xc[rr].x : (j == 1) ? xc[rr].y
                          : (j == 2) ? xc[rr].z : xc[rr].w;
                ull xx = pk2(xk, xk);
#pragma unroll
                for (int p = 0; p < 8; p++) pfma(acc[rr][p], xx, Wr[j][p]);
            }
        }

        // interleaved halving butterflies (two independent chains)
#pragma unroll
        for (int rr = 0; rr < 2; rr++) {
            if (lane & 16) {
#pragma unroll
                for (int j = 0; j < 4; j++) { ull t = acc[rr][j]; acc[rr][j] = acc[rr][j + 4]; acc[rr][j + 4] = t; }
            }
        }
#pragma unroll
        for (int rr = 0; rr < 2; rr++)
#pragma unroll
            for (int j = 0; j < 4; j++)
                acc[rr][j] = padd(acc[rr][j], __shfl_xor_sync(0xffffffffu, acc[rr][j + 4], 16));

#pragma unroll
        for (int rr = 0; rr < 2; rr++) {
            if (lane & 8) { ull t0 = acc[rr][0], t1 = acc[rr][1]; acc[rr][0] = acc[rr][2]; acc[rr][1] = acc[rr][3]; acc[rr][2] = t0; acc[rr][3] = t1; }
        }
#pragma unroll
        for (int rr = 0; rr < 2; rr++)
#pragma unroll
            for (int j = 0; j < 2; j++)
                acc[rr][j] = padd(acc[rr][j], __shfl_xor_sync(0xffffffffu, acc[rr][j + 2], 8));

#pragma unroll
        for (int rr = 0; rr < 2; rr++) {
            if (lane & 4) { ull t = acc[rr][0]; acc[rr][0] = acc[rr][1]; acc[rr][1] = t; }
        }
#pragma unroll
        for (int rr = 0; rr < 2; rr++)
            acc[rr][0] = padd(acc[rr][0], __shfl_xor_sync(0xffffffffu, acc[rr][1], 4));
#pragma unroll
        for (int rr = 0; rr < 2; rr++)
            acc[rr][0] = padd(acc[rr][0], __shfl_xor_sync(0xffffffffu, acc[rr][0], 2));
#pragma unroll
        for (int rr = 0; rr < 2; rr++)
            acc[rr][0] = padd(acc[rr][0], __shfl_xor_sync(0xffffffffu, acc[rr][0], 1));

        if ((lane & 3) == 0) {
            int col = ((lane & 16) ? 8 : 0) | ((lane & 8) ? 4 : 0) | ((lane & 4) ? 2 : 0);
            float2 f0 = up2(acc[0][0]);
            red_add_v2(g_h1 + (size_t)r * HID + col, f0.x, f0.y);
            if (two) {
                float2 f1 = up2(acc[1][0]);
                red_add_v2(g_h1 + (size_t)(r + 1) * HID + col, f1.x, f1.y);
            }
        }
    }
}

// ---------------- gather layer 1 (warp per node) + relu + W2 -> h2 ----------
__global__ __launch_bounds__(128) void k_gather1(const float* __restrict__ b1,
                                                 const float* __restrict__ W2, int N) {
    const int warp = (blockIdx.x * blockDim.x + threadIdx.x) >> 5;
    const int lane = threadIdx.x & 31;
    if (warp >= N) return;
    const int i = warp;
    const int eg = lane >> 2, p = lane & 3;

    const int beg = g_off[i], end = g_off[i + 1];
    const float di = g_dinv[i];

    float4 acc = make_float4(0.f, 0.f, 0.f, 0.f);
    for (int c = beg + eg; c < end; c += 8) {
        int s = g_esrc[c];
        float ds = g_dinv[s];
        float4 h = *(const float4*)(g_h1 + (size_t)s * HID + p * 4);
        acc.x = fmaf(ds, h.x, acc.x);
        acc.y = fmaf(ds, h.y, acc.y);
        acc.z = fmaf(ds, h.z, acc.z);
        acc.w = fmaf(ds, h.w, acc.w);
    }
    // reduce over eg (lane bits 2,3,4)
#pragma unroll
    for (int d = 16; d >= 4; d >>= 1) {
        acc.x += __shfl_xor_sync(0xffffffffu, acc.x, d);
        acc.y += __shfl_xor_sync(0xffffffffu, acc.y, d);
        acc.z += __shfl_xor_sync(0xffffffffu, acc.z, d);
        acc.w += __shfl_xor_sync(0xffffffffu, acc.w, d);
    }

    // lanes 0-3: self loop + bias + relu, then partial @W2
    float o0 = 0.f, o1 = 0.f;
    {
        float4 hs = *(const float4*)(g_h1 + (size_t)i * HID + p * 4);
        float4 bb = __ldg((const float4*)(b1 + p * 4));
        float d2 = di * di;
        float t0 = fmaxf(acc.x * di + d2 * hs.x + bb.x, 0.f);
        float t1 = fmaxf(acc.y * di + d2 * hs.y + bb.y, 0.f);
        float t2 = fmaxf(acc.z * di + d2 * hs.z + bb.z, 0.f);
        float t3 = fmaxf(acc.w * di + d2 * hs.w + bb.w, 0.f);
        int c = p * 4;
        o0 = t0 * __ldg(W2 + (c + 0) * NCLS + 0) + t1 * __ldg(W2 + (c + 1) * NCLS + 0)
           + t2 * __ldg(W2 + (c + 2) * NCLS + 0) + t3 * __ldg(W2 + (c + 3) * NCLS + 0);
        o1 = t0 * __ldg(W2 + (c + 0) * NCLS + 1) + t1 * __ldg(W2 + (c + 1) * NCLS + 1)
           + t2 * __ldg(W2 + (c + 2) * NCLS + 1) + t3 * __ldg(W2 + (c + 3) * NCLS + 1);
    }
    o0 += __shfl_xor_sync(0xffffffffu, o0, 2);
    o1 += __shfl_xor_sync(0xffffffffu, o1, 2);
    o0 += __shfl_xor_sync(0xffffffffu, o0, 1);
    o1 += __shfl_xor_sync(0xffffffffu, o1, 1);
    if (lane == 0)
        *(float2*)(g_h2 + (size_t)i * NCLS) = make_float2(o0, o1);
}

// ---------------- gather layer 2 (warp per node) + log_softmax -> out -------
__global__ __launch_bounds__(128) void k_gather2(const float* __restrict__ b2,
                                                 float* __restrict__ out, int N) {
    const int warp = (blockIdx.x * blockDim.x + threadIdx.x) >> 5;
    const int lane = threadIdx.x & 31;
    if (warp >= N) return;
    const int i = warp;
    const int beg = g_off[i], end = g_off[i + 1];
    const float di = g_dinv[i];

    float a0 = 0.f, a1 = 0.f;
    for (int c = beg + lane; c < end; c += 32) {
        int s = g_esrc[c];
        float ds = g_dinv[s];
        float2 h = *(const float2*)(g_h2 + (size_t)s * NCLS);
        a0 = fmaf(ds, h.x, a0);
        a1 = fmaf(ds, h.y, a1);
    }
#pragma unroll
    for (int d = 16; d >= 1; d >>= 1) {
        a0 += __shfl_xor_sync(0xffffffffu, a0, d);
        a1 += __shfl_xor_sync(0xffffffffu, a1, d);
    }
    if (lane == 0) {
        float d2 = di * di;
        float2 hs = *(const float2*)(g_h2 + (size_t)i * NCLS);
        float v0 = a0 * di + d2 * hs.x + __ldg(b2 + 0);
        float v1 = a1 * di + d2 * hs.y + __ldg(b2 + 1);
        float m = fmaxf(v0, v1);
        float lse = m + logf(expf(v0 - m) + expf(v1 - m));
        *(float2*)(out + (size_t)i * NCLS) = make_float2(v0 - lse, v1 - lse);
    }
}

// ---------------------------------------------------------------------------
extern "C" void kernel_launch(void* const* d_in, const int* in_sizes, int n_in,
                              void* d_out, int out_size) {
    const float* x = (const float*)d_in[0];
    const int* ei = (const int*)d_in[1];
    const float* W1 = (const float*)d_in[2];
    const float* b1 = (const float*)d_in[3];
    const float* W2 = (const float*)d_in[4];
    const float* b2 = (const float*)d_in[5];
    float* out = (float*)d_out;

    const int N = in_sizes[0] / F_IN;
    const int E = in_sizes[1] / 2;
    const int* src = ei;
    const int* dst = ei + E;
    const int NB = (N + SCAN_CH - 1) / SCAN_CH;

    k_zero<<<(N * HID + 255) / 256, 256>>>(N);
    k_deg<<<(E + 255) / 256, 256>>>(dst, E);
    k_scan1<<<NB, 512>>>(N);
    k_scan2<<<1, 256>>>(NB);
    k_scan3<<<(N + 255) / 256, 256>>>(N, E);
    k_fill<<<(E + 511) / 512, 512>>>(src, dst, E);
    k_gemm1<<<(N + RPB - 1) / RPB, 128>>>(x, W1, N);
    k_gather1<<<(N * 32 + 127) / 128, 128>>>(b1, W2, N);
    k_gather2<<<(N * 32 + 127) / 128, 128>>>(b2, out, N);
}

// round 6
// speedup vs baseline: 1.3053x; 1.2115x over previous
#include <cuda_runtime.h>
#include <cuda_bf16.h>
#include <math.h>

// ---------------------------------------------------------------------------
// 2-layer GCN via CSR-gather:
//   h1 = x @ W1        (3xTF32 mma.sync tensor-core GEMM, exact-ish)
//   CSR build: deg -> scan -> fill (edges bucketed by dst)
//   gather1: agg(h1)+self+b1, relu, @W2 -> h2   (warp per node)
//   gather2: agg(h2)+self+b2 -> log_softmax     (warp per node)
// edge_index arrives as int32.
// ---------------------------------------------------------------------------

#define F_IN 512
#define HID  16
#define NCLS 2
#define NMAX 131072
#define EMAX 3276800
#define SCAN_CH 2048

__device__ __align__(16) int   g_degcnt[NMAX];
__device__ __align__(16) int   g_incl[NMAX];
__device__ __align__(16) int   g_off[NMAX + 1];
__device__ __align__(16) int   g_cur[NMAX];
__device__ __align__(16) int   g_bsum[256];
__device__ __align__(16) int   g_boff[256];
__device__ __align__(16) float g_dinv[NMAX];
__device__ __align__(16) float g_h1[NMAX * HID];
__device__ __align__(16) float g_h2[NMAX * NCLS];
__device__ __align__(16) int   g_esrc[EMAX];
__device__ __align__(16) float g_w1hi[F_IN * HID];
__device__ __align__(16) float g_w1lo[F_IN * HID];

// ---------------- helpers ----------------
__device__ __forceinline__ unsigned cvt_tf32(float f) {
    unsigned r; asm("cvt.rna.tf32.f32 %0, %1;" : "=r"(r) : "f"(f)); return r;
}
__device__ __forceinline__ void mma_tf32(float* d, const unsigned* a,
                                         unsigned b0, unsigned b1) {
    asm("mma.sync.aligned.m16n8k8.row.col.f32.tf32.tf32.f32 "
        "{%0,%1,%2,%3}, {%4,%5,%6,%7}, {%8,%9}, {%0,%1,%2,%3};"
        : "+f"(d[0]), "+f"(d[1]), "+f"(d[2]), "+f"(d[3])
        : "r"(a[0]), "r"(a[1]), "r"(a[2]), "r"(a[3]), "r"(b0), "r"(b1));
}
__device__ __forceinline__ void cp_async16(void* smem_dst, const void* gmem_src) {
    unsigned sm;
    asm("{ .reg .u64 t; cvta.to.shared.u64 t, %1; cvt.u32.u64 %0, t; }"
        : "=r"(sm) : "l"(smem_dst));
    asm volatile("cp.async.cg.shared.global [%0], [%1], 16;"
                 :: "r"(sm), "l"(gmem_src) : "memory");
}
__device__ __forceinline__ void cp_commit() {
    asm volatile("cp.async.commit_group;" ::: "memory");
}
template <int NW>
__device__ __forceinline__ void cp_wait() {
    asm volatile("cp.async.wait_group %0;" :: "n"(NW) : "memory");
}

// ---------------- zero degree counters ----------------
__global__ void k_zero(int N) {
    int i = blockIdx.x * blockDim.x + threadIdx.x;
    if (i < N) g_degcnt[i] = 0;
}

// ---------------- degree count ----------------
__global__ void k_deg(const int* __restrict__ dst, int E) {
    int e = blockIdx.x * blockDim.x + threadIdx.x;
    if (e >= E) return;
    atomicAdd(&g_degcnt[dst[e]], 1);
}

// ---------------- W1 split into tf32 hi/lo ----------------
__global__ void k_wsplit(const float* __restrict__ W1) {
    int i = blockIdx.x * blockDim.x + threadIdx.x;
    if (i >= F_IN * HID) return;
    float w = W1[i];
    unsigned hi = cvt_tf32(w);
    float hif = __uint_as_float(hi);
    g_w1hi[i] = hif;
    g_w1lo[i] = __uint_as_float(cvt_tf32(w - hif));
}

// ---------------- GEMM1: h1 = x @ W1  via 3xTF32 mma ----------------
// 128 thr = 4 warps; warp = 16 rows; block = 64 rows. KC=32 chunk staged in
// smem (x stride 36, W slices stride 24 -> conflict-free frag loads).
#define KC 32
#define GROWS 64
#define XSTR 36
#define WSTR 24

__global__ __launch_bounds__(128) void k_gemm1(const float* __restrict__ x, int N) {
    __shared__ float xs[GROWS * XSTR];
    __shared__ float wh[KC * WSTR];
    __shared__ float wl[KC * WSTR];
    const int tid = threadIdx.x;
    const int lane = tid & 31, w = tid >> 5;
    const int row0 = blockIdx.x * GROWS;
    const int wrow = w * 16;
    const int tr = lane >> 2, tc = lane & 3;

    float d[2][4] = {{0.f, 0.f, 0.f, 0.f}, {0.f, 0.f, 0.f, 0.f}};

    const int wr = tid >> 2, wq = tid & 3;   // W-slice load coords

    for (int ch = 0; ch < F_IN / KC; ch++) {
        __syncthreads();   // previous chunk's compute done before overwrite
#pragma unroll
        for (int i = 0; i < 4; i++) {
            int idx = tid + 128 * i;        // 0..511 float4 slots
            int r = idx >> 3, q = idx & 7;
            int gr = row0 + r; if (gr >= N) gr = N - 1;
            cp_async16(xs + r * XSTR + q * 4,
                       x + (size_t)gr * F_IN + ch * KC + q * 4);
        }
        cp_async16(wh + wr * WSTR + wq * 4, g_w1hi + (ch * KC + wr) * HID + wq * 4);
        cp_async16(wl + wr * WSTR + wq * 4, g_w1lo + (ch * KC + wr) * HID + wq * 4);
        cp_commit();
        cp_wait<0>();
        __syncthreads();

#pragma unroll
        for (int ks = 0; ks < KC / 8; ks++) {
            int kb = ks * 8;
            float a_f[4];
            a_f[0] = xs[(wrow + tr) * XSTR + kb + tc];
            a_f[1] = xs[(wrow + tr + 8) * XSTR + kb + tc];
            a_f[2] = xs[(wrow + tr) * XSTR + kb + tc + 4];
            a_f[3] = xs[(wrow + tr + 8) * XSTR + kb + tc + 4];
            unsigned ah[4], al[4];
#pragma unroll
            for (int j = 0; j < 4; j++) {
                ah[j] = cvt_tf32(a_f[j]);
                al[j] = cvt_tf32(a_f[j] - __uint_as_float(ah[j]));
            }
#pragma unroll
            for (int nt = 0; nt < 2; nt++) {
                int b0i = (kb + tc) * WSTR + nt * 8 + tr;
                int b1i = b0i + 4 * WSTR;
                unsigned bh0 = __float_as_uint(wh[b0i]);
                unsigned bh1 = __float_as_uint(wh[b1i]);
                unsigned bl0 = __float_as_uint(wl[b0i]);
                unsigned bl1 = __float_as_uint(wl[b1i]);
                mma_tf32(d[nt], ah, bh0, bh1);
                mma_tf32(d[nt], al, bh0, bh1);
                mma_tf32(d[nt], ah, bl0, bl1);
            }
        }
    }

    int r0 = row0 + wrow + tr, r1 = r0 + 8;
#pragma unroll
    for (int nt = 0; nt < 2; nt++) {
        int c = nt * 8 + 2 * tc;
        if (r0 < N)
            *(float2*)(g_h1 + (size_t)r0 * HID + c) = make_float2(d[nt][0], d[nt][1]);
        if (r1 < N)
            *(float2*)(g_h1 + (size_t)r1 * HID + c) = make_float2(d[nt][2], d[nt][3]);
    }
}

// ---------------- scan pass 1 ----------------
__global__ __launch_bounds__(512) void k_scan1(int N) {
    __shared__ int wsum[16];
    const int t = threadIdx.x;
    const int base = blockIdx.x * SCAN_CH + t * 4;
    int v0 = (base + 0 < N) ? g_degcnt[base + 0] : 0;
    int v1 = (base + 1 < N) ? g_degcnt[base + 1] : 0;
    int v2 = (base + 2 < N) ? g_degcnt[base + 2] : 0;
    int v3 = (base + 3 < N) ? g_degcnt[base + 3] : 0;
    int s1 = v0 + v1, s2 = s1 + v2, s3 = s2 + v3;
    int tot = s3;

    int lane = t & 31, w = t >> 5;
    int sc = tot;
#pragma unroll
    for (int d = 1; d < 32; d <<= 1) {
        int u = __shfl_up_sync(0xffffffffu, sc, d);
        if (lane >= d) sc += u;
    }
    if (lane == 31) wsum[w] = sc;
    __syncthreads();
    if (w == 0) {
        int xv = (lane < 16) ? wsum[lane] : 0;
#pragma unroll
        for (int d = 1; d < 16; d <<= 1) {
            int u = __shfl_up_sync(0xffffffffu, xv, d);
            if (lane >= d) xv += u;
        }
        if (lane < 16) wsum[lane] = xv;
    }
    __syncthreads();
    int woff = (w > 0) ? wsum[w - 1] : 0;
    int excl = woff + sc - tot;
    if (base + 0 < N) g_incl[base + 0] = excl + v0;
    if (base + 1 < N) g_incl[base + 1] = excl + s1;
    if (base + 2 < N) g_incl[base + 2] = excl + s2;
    if (base + 3 < N) g_incl[base + 3] = excl + s3;
    if (t == 0) g_bsum[blockIdx.x] = wsum[15];
}

// ---------------- scan pass 2 ----------------
__global__ void k_scan2(int NB) {
    __shared__ int sm[256];
    int t = threadIdx.x;
    sm[t] = (t < NB) ? g_bsum[t] : 0;
    __syncthreads();
    if (t == 0) {
        int run = 0;
        for (int b = 0; b < NB; b++) { int v = sm[b]; sm[b] = run; run += v; }
    }
    __syncthreads();
    if (t < NB) g_boff[t] = sm[t];
}

// ---------------- scan pass 3 ----------------
__global__ void k_scan3(int N, int E) {
    int i = blockIdx.x * blockDim.x + threadIdx.x;
    if (i >= N) return;
    int deg = g_degcnt[i];
    int off = g_boff[i / SCAN_CH] + g_incl[i] - deg;
    g_off[i] = off;
    g_cur[i] = off;
    g_dinv[i] = rsqrtf((float)(deg + 1));
    if (i == 0) g_off[N] = E;
}

// ---------------- fill CSR edge list ----------------
__global__ void k_fill(const int* __restrict__ src,
                       const int* __restrict__ dst, int E) {
    int e = blockIdx.x * blockDim.x + threadIdx.x;
    if (e >= E) return;
    int d = dst[e];
    int slot = atomicAdd(&g_cur[d], 1);
    g_esrc[slot] = src[e];
}

// ---------------- gather layer 1 (warp per node) + relu + W2 -> h2 ----------
__global__ __launch_bounds__(128) void k_gather1(const float* __restrict__ b1,
                                                 const float* __restrict__ W2, int N) {
    const int warp = (blockIdx.x * blockDim.x + threadIdx.x) >> 5;
    const int lane = threadIdx.x & 31;
    if (warp >= N) return;
    const int i = warp;
    const int eg = lane >> 2, p = lane & 3;

    const int beg = g_off[i], end = g_off[i + 1];
    const float di = g_dinv[i];

    float4 acc = make_float4(0.f, 0.f, 0.f, 0.f);
    for (int c = beg + eg; c < end; c += 8) {
        int s = g_esrc[c];
        float ds = g_dinv[s];
        float4 h = *(const float4*)(g_h1 + (size_t)s * HID + p * 4);
        acc.x = fmaf(ds, h.x, acc.x);
        acc.y = fmaf(ds, h.y, acc.y);
        acc.z = fmaf(ds, h.z, acc.z);
        acc.w = fmaf(ds, h.w, acc.w);
    }
#pragma unroll
    for (int d = 16; d >= 4; d >>= 1) {
        acc.x += __shfl_xor_sync(0xffffffffu, acc.x, d);
        acc.y += __shfl_xor_sync(0xffffffffu, acc.y, d);
        acc.z += __shfl_xor_sync(0xffffffffu, acc.z, d);
        acc.w += __shfl_xor_sync(0xffffffffu, acc.w, d);
    }

    float o0 = 0.f, o1 = 0.f;
    {
        float4 hs = *(const float4*)(g_h1 + (size_t)i * HID + p * 4);
        float4 bb = __ldg((const float4*)(b1 + p * 4));
        float d2 = di * di;
        float t0 = fmaxf(acc.x * di + d2 * hs.x + bb.x, 0.f);
        float t1 = fmaxf(acc.y * di + d2 * hs.y + bb.y, 0.f);
        float t2 = fmaxf(acc.z * di + d2 * hs.z + bb.z, 0.f);
        float t3 = fmaxf(acc.w * di + d2 * hs.w + bb.w, 0.f);
        int c = p * 4;
        o0 = t0 * __ldg(W2 + (c + 0) * NCLS + 0) + t1 * __ldg(W2 + (c + 1) * NCLS + 0)
           + t2 * __ldg(W2 + (c + 2) * NCLS + 0) + t3 * __ldg(W2 + (c + 3) * NCLS + 0);
        o1 = t0 * __ldg(W2 + (c + 0) * NCLS + 1) + t1 * __ldg(W2 + (c + 1) * NCLS + 1)
           + t2 * __ldg(W2 + (c + 2) * NCLS + 1) + t3 * __ldg(W2 + (c + 3) * NCLS + 1);
    }
    o0 += __shfl_xor_sync(0xffffffffu, o0, 2);
    o1 += __shfl_xor_sync(0xffffffffu, o1, 2);
    o0 += __shfl_xor_sync(0xffffffffu, o0, 1);
    o1 += __shfl_xor_sync(0xffffffffu, o1, 1);
    if (lane == 0)
        *(float2*)(g_h2 + (size_t)i * NCLS) = make_float2(o0, o1);
}

// ---------------- gather layer 2 (warp per node) + log_softmax -> out -------
__global__ __launch_bounds__(128) void k_gather2(const float* __restrict__ b2,
                                                 float* __restrict__ out, int N) {
    const int warp = (blockIdx.x * blockDim.x + threadIdx.x) >> 5;
    const int lane = threadIdx.x & 31;
    if (warp >= N) return;
    const int i = warp;
    const int beg = g_off[i], end = g_off[i + 1];
    const float di = g_dinv[i];

    float a0 = 0.f, a1 = 0.f;
    for (int c = beg + lane; c < end; c += 32) {
        int s = g_esrc[c];
        float ds = g_dinv[s];
        float2 h = *(const float2*)(g_h2 + (size_t)s * NCLS);
        a0 = fmaf(ds, h.x, a0);
        a1 = fmaf(ds, h.y, a1);
    }
#pragma unroll
    for (int d = 16; d >= 1; d >>= 1) {
        a0 += __shfl_xor_sync(0xffffffffu, a0, d);
        a1 += __shfl_xor_sync(0xffffffffu, a1, d);
    }
    if (lane == 0) {
        float d2 = di * di;
        float2 hs = *(const float2*)(g_h2 + (size_t)i * NCLS);
        float v0 = a0 * di + d2 * hs.x + __ldg(b2 + 0);
        float v1 = a1 * di + d2 * hs.y + __ldg(b2 + 1);
        float m = fmaxf(v0, v1);
        float lse = m + logf(expf(v0 - m) + expf(v1 - m));
        *(float2*)(out + (size_t)i * NCLS) = make_float2(v0 - lse, v1 - lse);
    }
}

// ---------------------------------------------------------------------------
extern "C" void kernel_launch(void* const* d_in, const int* in_sizes, int n_in,
                              void* d_out, int out_size) {
    const float* x = (const float*)d_in[0];
    const int* ei = (const int*)d_in[1];
    const float* W1 = (const float*)d_in[2];
    const float* b1 = (const float*)d_in[3];
    const float* W2 = (const float*)d_in[4];
    const float* b2 = (const float*)d_in[5];
    float* out = (float*)d_out;

    const int N = in_sizes[0] / F_IN;
    const int E = in_sizes[1] / 2;
    const int* src = ei;
    const int* dst = ei + E;
    const int NB = (N + SCAN_CH - 1) / SCAN_CH;

    // slot 3 (profiled) = k_gemm1
    k_zero<<<(N + 255) / 256, 256>>>(N);                       // 0
    k_deg<<<(E + 255) / 256, 256>>>(dst, E);                   // 1
    k_wsplit<<<(F_IN * HID + 255) / 256, 256>>>(W1);           // 2
    k_gemm1<<<(N + GROWS - 1) / GROWS, 128>>>(x, N);           // 3
    k_scan1<<<NB, 512>>>(N);                                   // 4
    k_scan2<<<1, 256>>>(NB);                                   // 5
    k_scan3<<<(N + 255) / 256, 256>>>(N, E);                   // 6
    k_fill<<<(E + 511) / 512, 512>>>(src, dst, E);             // 7
    k_gather1<<<(N * 32 + 127) / 128, 128>>>(b1, W2, N);       // 8
    k_gather2<<<(N * 32 + 127) / 128, 128>>>(b2, out, N);      // 9
}

// round 7
// speedup vs baseline: 1.3884x; 1.0636x over previous
#include <cuda_runtime.h>
#include <cuda_bf16.h>
#include <math.h>

// ---------------------------------------------------------------------------
// 2-layer GCN via CSR-gather:
//   h1 = x @ W1        (3xTF32 mma.sync, 2-stage cp.async pipeline)
//   CSR build: deg -> scan -> fill (edges bucketed by dst, packed (src,dinv))
//   gather1: agg(h1)+self+b1, relu, @W2 -> h2   (warp per node)
//   gather2: agg(h2)+self+b2 -> log_softmax     (warp per node)
// edge_index arrives as int32.
// ---------------------------------------------------------------------------

#define F_IN 512
#define HID  16
#define NCLS 2
#define NMAX 131072
#define EMAX 3276800
#define SCAN_CH 2048

__device__ __align__(16) int   g_degcnt[NMAX];
__device__ __align__(16) int   g_incl[NMAX];
__device__ __align__(16) int   g_off[NMAX + 1];
__device__ __align__(16) int   g_cur[NMAX];
__device__ __align__(16) int   g_bsum[256];
__device__ __align__(16) int   g_boff[256];
__device__ __align__(16) float g_dinv[NMAX];
__device__ __align__(16) float g_h1[NMAX * HID];
__device__ __align__(16) float g_h2[NMAX * NCLS];
__device__ __align__(16) int2  g_epack[EMAX];   // {src, bits(dinv[src])}
__device__ __align__(16) float g_w1hi[F_IN * HID];
__device__ __align__(16) float g_w1lo[F_IN * HID];

// ---------------- helpers ----------------
__device__ __forceinline__ unsigned cvt_tf32(float f) {
    unsigned r; asm("cvt.rna.tf32.f32 %0, %1;" : "=r"(r) : "f"(f)); return r;
}
__device__ __forceinline__ void mma_tf32(float* d, const unsigned* a,
                                         unsigned b0, unsigned b1) {
    asm("mma.sync.aligned.m16n8k8.row.col.f32.tf32.tf32.f32 "
        "{%0,%1,%2,%3}, {%4,%5,%6,%7}, {%8,%9}, {%0,%1,%2,%3};"
        : "+f"(d[0]), "+f"(d[1]), "+f"(d[2]), "+f"(d[3])
        : "r"(a[0]), "r"(a[1]), "r"(a[2]), "r"(a[3]), "r"(b0), "r"(b1));
}
__device__ __forceinline__ void cp_async16(void* smem_dst, const void* gmem_src) {
    unsigned sm;
    asm("{ .reg .u64 t; cvta.to.shared.u64 t, %1; cvt.u32.u64 %0, t; }"
        : "=r"(sm) : "l"(smem_dst));
    asm volatile("cp.async.cg.shared.global [%0], [%1], 16;"
                 :: "r"(sm), "l"(gmem_src) : "memory");
}
__device__ __forceinline__ void cp_commit() {
    asm volatile("cp.async.commit_group;" ::: "memory");
}
template <int NW>
__device__ __forceinline__ void cp_wait() {
    asm volatile("cp.async.wait_group %0;" :: "n"(NW) : "memory");
}

// ---------------- zero degree counters ----------------
__global__ void k_zero(int N) {
    int i = blockIdx.x * blockDim.x + threadIdx.x;
    if (i < N) g_degcnt[i] = 0;
}

// ---------------- degree count (4 edges / thread) ----------------
__global__ void k_deg(const int* __restrict__ dst, int E) {
    int i = blockIdx.x * blockDim.x + threadIdx.x;
    int base = i * 4;
    if (base + 3 < E) {
        int4 d = *(const int4*)(dst + base);
        atomicAdd(&g_degcnt[d.x], 1);
        atomicAdd(&g_degcnt[d.y], 1);
        atomicAdd(&g_degcnt[d.z], 1);
        atomicAdd(&g_degcnt[d.w], 1);
    } else {
        for (int e = base; e < E; e++) atomicAdd(&g_degcnt[dst[e]], 1);
    }
}

// ---------------- W1 split into tf32 hi/lo ----------------
__global__ void k_wsplit(const float* __restrict__ W1) {
    int i = blockIdx.x * blockDim.x + threadIdx.x;
    if (i >= F_IN * HID) return;
    float w = W1[i];
    unsigned hi = cvt_tf32(w);
    float hif = __uint_as_float(hi);
    g_w1hi[i] = hif;
    g_w1lo[i] = __uint_as_float(cvt_tf32(w - hif));
}

// ---------------- GEMM1: h1 = x @ W1  via 3xTF32 mma, double-buffered -------
#define KC 32
#define GROWS 64
#define XSTR 36
#define WSTR 24
#define NCHUNK (F_IN / KC)

__global__ __launch_bounds__(128) void k_gemm1(const float* __restrict__ x, int N) {
    __shared__ float xs[2][GROWS * XSTR];
    __shared__ float wh[2][KC * WSTR];
    __shared__ float wl[2][KC * WSTR];
    const int tid = threadIdx.x;
    const int lane = tid & 31, w = tid >> 5;
    const int row0 = blockIdx.x * GROWS;
    const int wrow = w * 16;
    const int tr = lane >> 2, tc = lane & 3;
    const int wr = tid >> 2, wq = tid & 3;

    float d[2][4] = {{0.f, 0.f, 0.f, 0.f}, {0.f, 0.f, 0.f, 0.f}};

    // row clamps for the 4 x-tile loads this thread performs
    int lr[4], lq = tid & 7;
#pragma unroll
    for (int i = 0; i < 4; i++) {
        int idx = tid + 128 * i;
        lr[i] = idx >> 3;
    }

    // prefetch chunk 0 -> buffer 0
#pragma unroll
    for (int i = 0; i < 4; i++) {
        int gr = row0 + lr[i]; if (gr >= N) gr = N - 1;
        cp_async16(xs[0] + lr[i] * XSTR + lq * 4, x + (size_t)gr * F_IN + lq * 4);
    }
    cp_async16(wh[0] + wr * WSTR + wq * 4, g_w1hi + wr * HID + wq * 4);
    cp_async16(wl[0] + wr * WSTR + wq * 4, g_w1lo + wr * HID + wq * 4);
    cp_commit();

    for (int ch = 0; ch < NCHUNK; ch++) {
        const int b = ch & 1;
        if (ch + 1 < NCHUNK) {
            int kc = (ch + 1) * KC;
#pragma unroll
            for (int i = 0; i < 4; i++) {
                int gr = row0 + lr[i]; if (gr >= N) gr = N - 1;
                cp_async16(xs[b ^ 1] + lr[i] * XSTR + lq * 4,
                           x + (size_t)gr * F_IN + kc + lq * 4);
            }
            cp_async16(wh[b ^ 1] + wr * WSTR + wq * 4, g_w1hi + (kc + wr) * HID + wq * 4);
            cp_async16(wl[b ^ 1] + wr * WSTR + wq * 4, g_w1lo + (kc + wr) * HID + wq * 4);
            cp_commit();
            cp_wait<1>();
        } else {
            cp_wait<0>();
        }
        __syncthreads();

        const float* xb = xs[b];
        const float* whb = wh[b];
        const float* wlb = wl[b];
#pragma unroll
        for (int ks = 0; ks < KC / 8; ks++) {
            int kb = ks * 8;
            float a_f[4];
            a_f[0] = xb[(wrow + tr) * XSTR + kb + tc];
            a_f[1] = xb[(wrow + tr + 8) * XSTR + kb + tc];
            a_f[2] = xb[(wrow + tr) * XSTR + kb + tc + 4];
            a_f[3] = xb[(wrow + tr + 8) * XSTR + kb + tc + 4];
            unsigned ah[4], al[4];
#pragma unroll
            for (int j = 0; j < 4; j++) {
                ah[j] = cvt_tf32(a_f[j]);
                al[j] = cvt_tf32(a_f[j] - __uint_as_float(ah[j]));
            }
#pragma unroll
            for (int nt = 0; nt < 2; nt++) {
                int b0i = (kb + tc) * WSTR + nt * 8 + tr;
                int b1i = b0i + 4 * WSTR;
                unsigned bh0 = __float_as_uint(whb[b0i]);
                unsigned bh1 = __float_as_uint(whb[b1i]);
                unsigned bl0 = __float_as_uint(wlb[b0i]);
                unsigned bl1 = __float_as_uint(wlb[b1i]);
                mma_tf32(d[nt], ah, bh0, bh1);
                mma_tf32(d[nt], al, bh0, bh1);
                mma_tf32(d[nt], ah, bl0, bl1);
            }
        }
        __syncthreads();   // compute done before buffer b is re-filled
    }

    int r0 = row0 + wrow + tr, r1 = r0 + 8;
#pragma unroll
    for (int nt = 0; nt < 2; nt++) {
        int c = nt * 8 + 2 * tc;
        if (r0 < N)
            *(float2*)(g_h1 + (size_t)r0 * HID + c) = make_float2(d[nt][0], d[nt][1]);
        if (r1 < N)
            *(float2*)(g_h1 + (size_t)r1 * HID + c) = make_float2(d[nt][2], d[nt][3]);
    }
}

// ---------------- scan pass 1 ----------------
__global__ __launch_bounds__(512) void k_scan1(int N) {
    __shared__ int wsum[16];
    const int t = threadIdx.x;
    const int base = blockIdx.x * SCAN_CH + t * 4;
    int v0 = (base + 0 < N) ? g_degcnt[base + 0] : 0;
    int v1 = (base + 1 < N) ? g_degcnt[base + 1] : 0;
    int v2 = (base + 2 < N) ? g_degcnt[base + 2] : 0;
    int v3 = (base + 3 < N) ? g_degcnt[base + 3] : 0;
    int s1 = v0 + v1, s2 = s1 + v2, s3 = s2 + v3;
    int tot = s3;

    int lane = t & 31, w = t >> 5;
    int sc = tot;
#pragma unroll
    for (int d = 1; d < 32; d <<= 1) {
        int u = __shfl_up_sync(0xffffffffu, sc, d);
        if (lane >= d) sc += u;
    }
    if (lane == 31) wsum[w] = sc;
    __syncthreads();
    if (w == 0) {
        int xv = (lane < 16) ? wsum[lane] : 0;
#pragma unroll
        for (int d = 1; d < 16; d <<= 1) {
            int u = __shfl_up_sync(0xffffffffu, xv, d);
            if (lane >= d) xv += u;
        }
        if (lane < 16) wsum[lane] = xv;
    }
    __syncthreads();
    int woff = (w > 0) ? wsum[w - 1] : 0;
    int excl = woff + sc - tot;
    if (base + 0 < N) g_incl[base + 0] = excl + v0;
    if (base + 1 < N) g_incl[base + 1] = excl + s1;
    if (base + 2 < N) g_incl[base + 2] = excl + s2;
    if (base + 3 < N) g_incl[base + 3] = excl + s3;
    if (t == 0) g_bsum[blockIdx.x] = wsum[15];
}

// ---------------- scan pass 2: warp-scan of block sums ----------------
__global__ void k_scan2(int NB) {
    __shared__ int ws[8];
    int t = threadIdx.x;            // 256 threads
    int lane = t & 31, w = t >> 5;
    int v = (t < NB) ? g_bsum[t] : 0;
    int s = v;
#pragma unroll
    for (int d = 1; d < 32; d <<= 1) {
        int u = __shfl_up_sync(0xffffffffu, s, d);
        if (lane >= d) s += u;
    }
    if (lane == 31) ws[w] = s;
    __syncthreads();
    if (w == 0 && lane < 8) {
        int xv = ws[lane];
#pragma unroll
        for (int d = 1; d < 8; d <<= 1) {
            int u = __shfl_up_sync(0xffu, xv, d);
            if (lane >= d) xv += u;
        }
        ws[lane] = xv;
    }
    __syncthreads();
    int off = (w > 0) ? ws[w - 1] : 0;
    if (t < NB) g_boff[t] = off + s - v;   // exclusive
}

// ---------------- scan pass 3 ----------------
__global__ void k_scan3(int N, int E) {
    int i = blockIdx.x * blockDim.x + threadIdx.x;
    if (i >= N) return;
    int deg = g_degcnt[i];
    int off = g_boff[i / SCAN_CH] + g_incl[i] - deg;
    g_off[i] = off;
    g_cur[i] = off;
    g_dinv[i] = rsqrtf((float)(deg + 1));
    if (i == 0) g_off[N] = E;
}

// ---------------- fill CSR edge list (packed src + dinv[src]) ----------------
__global__ void k_fill(const int* __restrict__ src,
                       const int* __restrict__ dst, int E) {
    int e = blockIdx.x * blockDim.x + threadIdx.x;
    if (e >= E) return;
    int d = dst[e];
    int s = src[e];
    int slot = atomicAdd(&g_cur[d], 1);
    g_epack[slot] = make_int2(s, __float_as_int(g_dinv[s]));
}

// ---------------- gather layer 1 (warp per node) + relu + W2 -> h2 ----------
__global__ __launch_bounds__(128) void k_gather1(const float* __restrict__ b1,
                                                 const float* __restrict__ W2, int N) {
    const int warp = (blockIdx.x * blockDim.x + threadIdx.x) >> 5;
    const int lane = threadIdx.x & 31;
    if (warp >= N) return;
    const int i = warp;
    const int eg = lane >> 2, p = lane & 3;

    const int beg = g_off[i], end = g_off[i + 1];
    const float di = g_dinv[i];

    float4 acc = make_float4(0.f, 0.f, 0.f, 0.f);
    for (int c = beg + eg; c < end; c += 8) {
        int2 pk = g_epack[c];
        float ds = __int_as_float(pk.y);
        float4 h = *(const float4*)(g_h1 + (size_t)pk.x * HID + p * 4);
        acc.x = fmaf(ds, h.x, acc.x);
        acc.y = fmaf(ds, h.y, acc.y);
        acc.z = fmaf(ds, h.z, acc.z);
        acc.w = fmaf(ds, h.w, acc.w);
    }
#pragma unroll
    for (int d = 16; d >= 4; d >>= 1) {
        acc.x += __shfl_xor_sync(0xffffffffu, acc.x, d);
        acc.y += __shfl_xor_sync(0xffffffffu, acc.y, d);
        acc.z += __shfl_xor_sync(0xffffffffu, acc.z, d);
        acc.w += __shfl_xor_sync(0xffffffffu, acc.w, d);
    }

    float o0 = 0.f, o1 = 0.f;
    {
        float4 hs = *(const float4*)(g_h1 + (size_t)i * HID + p * 4);
        float4 bb = __ldg((const float4*)(b1 + p * 4));
        float d2 = di * di;
        float t0 = fmaxf(acc.x * di + d2 * hs.x + bb.x, 0.f);
        float t1 = fmaxf(acc.y * di + d2 * hs.y + bb.y, 0.f);
        float t2 = fmaxf(acc.z * di + d2 * hs.z + bb.z, 0.f);
        float t3 = fmaxf(acc.w * di + d2 * hs.w + bb.w, 0.f);
        int c = p * 4;
        o0 = t0 * __ldg(W2 + (c + 0) * NCLS + 0) + t1 * __ldg(W2 + (c + 1) * NCLS + 0)
           + t2 * __ldg(W2 + (c + 2) * NCLS + 0) + t3 * __ldg(W2 + (c + 3) * NCLS + 0);
        o1 = t0 * __ldg(W2 + (c + 0) * NCLS + 1) + t1 * __ldg(W2 + (c + 1) * NCLS + 1)
           + t2 * __ldg(W2 + (c + 2) * NCLS + 1) + t3 * __ldg(W2 + (c + 3) * NCLS + 1);
    }
    o0 += __shfl_xor_sync(0xffffffffu, o0, 2);
    o1 += __shfl_xor_sync(0xffffffffu, o1, 2);
    o0 += __shfl_xor_sync(0xffffffffu, o0, 1);
    o1 += __shfl_xor_sync(0xffffffffu, o1, 1);
    if (lane == 0)
        *(float2*)(g_h2 + (size_t)i * NCLS) = make_float2(o0, o1);
}

// ---------------- gather layer 2 (warp per node) + log_softmax -> out -------
__global__ __launch_bounds__(128) void k_gather2(const float* __restrict__ b2,
                                                 float* __restrict__ out, int N) {
    const int warp = (blockIdx.x * blockDim.x + threadIdx.x) >> 5;
    const int lane = threadIdx.x & 31;
    if (warp >= N) return;
    const int i = warp;
    const int beg = g_off[i], end = g_off[i + 1];
    const float di = g_dinv[i];

    float a0 = 0.f, a1 = 0.f;
    for (int c = beg + lane; c < end; c += 32) {
        int2 pk = g_epack[c];
        float ds = __int_as_float(pk.y);
        float2 h = *(const float2*)(g_h2 + (size_t)pk.x * NCLS);
        a0 = fmaf(ds, h.x, a0);
        a1 = fmaf(ds, h.y, a1);
    }
#pragma unroll
    for (int d = 16; d >= 1; d >>= 1) {
        a0 += __shfl_xor_sync(0xffffffffu, a0, d);
        a1 += __shfl_xor_sync(0xffffffffu, a1, d);
    }
    if (lane == 0) {
        float d2 = di * di;
        float2 hs = *(const float2*)(g_h2 + (size_t)i * NCLS);
        float v0 = a0 * di + d2 * hs.x + __ldg(b2 + 0);
        float v1 = a1 * di + d2 * hs.y + __ldg(b2 + 1);
        float m = fmaxf(v0, v1);
        float lse = m + logf(expf(v0 - m) + expf(v1 - m));
        *(float2*)(out + (size_t)i * NCLS) = make_float2(v0 - lse, v1 - lse);
    }
}

// ---------------------------------------------------------------------------
extern "C" void kernel_launch(void* const* d_in, const int* in_sizes, int n_in,
                              void* d_out, int out_size) {
    const float* x = (const float*)d_in[0];
    const int* ei = (const int*)d_in[1];
    const float* W1 = (const float*)d_in[2];
    const float* b1 = (const float*)d_in[3];
    const float* W2 = (const float*)d_in[4];
    const float* b2 = (const float*)d_in[5];
    float* out = (float*)d_out;

    const int N = in_sizes[0] / F_IN;
    const int E = in_sizes[1] / 2;
    const int* src = ei;
    const int* dst = ei + E;
    const int NB = (N + SCAN_CH - 1) / SCAN_CH;

    // slot 3 (profiled) = k_gemm1
    k_zero<<<(N + 255) / 256, 256>>>(N);                        // 0
    k_deg<<<(E / 4 + 255) / 256, 256>>>(dst, E);                // 1
    k_wsplit<<<(F_IN * HID + 255) / 256, 256>>>(W1);            // 2
    k_gemm1<<<(N + GROWS - 1) / GROWS, 128>>>(x, N);            // 3
    k_scan1<<<NB, 512>>>(N);                                    // 4
    k_scan2<<<1, 256>>>(NB);                                    // 5
    k_scan3<<<(N + 255) / 256, 256>>>(N, E);                    // 6
    k_fill<<<(E + 511) / 512, 512>>>(src, dst, E);              // 7
    k_gather1<<<(N * 32 + 127) / 128, 128>>>(b1, W2, N);        // 8
    k_gather2<<<(N * 32 + 127) / 128, 128>>>(b2, out, N);       // 9
}

// round 8
// speedup vs baseline: 1.5319x; 1.1034x over previous
#include <cuda_runtime.h>
#include <cuda_bf16.h>
#include <math.h>

// ---------------------------------------------------------------------------
// 2-layer GCN via CSR-gather, with forked-stream graph capture:
//   branch A (s2):  wsplit -> gemm1 (3xTF32 mma, double-buffered cp.async)
//   branch B (main): zero -> deg -> scan1..3 -> fill (CSR by dst)
//   join -> gather1 (agg+relu+W2) -> gather2 (agg+log_softmax)
// edge_index arrives as int32.
// ---------------------------------------------------------------------------

#define F_IN 512
#define HID  16
#define NCLS 2
#define NMAX 131072
#define EMAX 3276800
#define SCAN_CH 2048

__device__ __align__(16) int   g_degcnt[NMAX];
__device__ __align__(16) int   g_incl[NMAX];
__device__ __align__(16) int   g_off[NMAX + 1];
__device__ __align__(16) int   g_cur[NMAX];
__device__ __align__(16) int   g_bsum[256];
__device__ __align__(16) int   g_boff[256];
__device__ __align__(16) float g_dinv[NMAX];
__device__ __align__(16) float g_h1[NMAX * HID];
__device__ __align__(16) float g_h2[NMAX * NCLS];
__device__ __align__(16) int2  g_epack[EMAX];   // {src, bits(dinv[src])}
__device__ __align__(16) float g_w1hi[F_IN * HID];
__device__ __align__(16) float g_w1lo[F_IN * HID];

// ---------------- helpers ----------------
__device__ __forceinline__ unsigned cvt_tf32(float f) {
    unsigned r; asm("cvt.rna.tf32.f32 %0, %1;" : "=r"(r) : "f"(f)); return r;
}
__device__ __forceinline__ void mma_tf32(float* d, const unsigned* a,
                                         unsigned b0, unsigned b1) {
    asm("mma.sync.aligned.m16n8k8.row.col.f32.tf32.tf32.f32 "
        "{%0,%1,%2,%3}, {%4,%5,%6,%7}, {%8,%9}, {%0,%1,%2,%3};"
        : "+f"(d[0]), "+f"(d[1]), "+f"(d[2]), "+f"(d[3])
        : "r"(a[0]), "r"(a[1]), "r"(a[2]), "r"(a[3]), "r"(b0), "r"(b1));
}
__device__ __forceinline__ void cp_async16(void* smem_dst, const void* gmem_src) {
    unsigned sm;
    asm("{ .reg .u64 t; cvta.to.shared.u64 t, %1; cvt.u32.u64 %0, t; }"
        : "=r"(sm) : "l"(smem_dst));
    asm volatile("cp.async.cg.shared.global [%0], [%1], 16;"
                 :: "r"(sm), "l"(gmem_src) : "memory");
}
__device__ __forceinline__ void cp_commit() {
    asm volatile("cp.async.commit_group;" ::: "memory");
}
template <int NW>
__device__ __forceinline__ void cp_wait() {
    asm volatile("cp.async.wait_group %0;" :: "n"(NW) : "memory");
}

// ---------------- zero degree counters ----------------
__global__ void k_zero(int N) {
    int i = blockIdx.x * blockDim.x + threadIdx.x;
    if (i < N) g_degcnt[i] = 0;
}

// ---------------- degree count (4 edges / thread) ----------------
__global__ void k_deg(const int* __restrict__ dst, int E) {
    int i = blockIdx.x * blockDim.x + threadIdx.x;
    int base = i * 4;
    if (base + 3 < E) {
        int4 d = *(const int4*)(dst + base);
        atomicAdd(&g_degcnt[d.x], 1);
        atomicAdd(&g_degcnt[d.y], 1);
        atomicAdd(&g_degcnt[d.z], 1);
        atomicAdd(&g_degcnt[d.w], 1);
    } else {
        for (int e = base; e < E; e++) atomicAdd(&g_degcnt[dst[e]], 1);
    }
}

// ---------------- W1 split into tf32 hi/lo ----------------
__global__ void k_wsplit(const float* __restrict__ W1) {
    int i = blockIdx.x * blockDim.x + threadIdx.x;
    if (i >= F_IN * HID) return;
    float w = W1[i];
    unsigned hi = cvt_tf32(w);
    float hif = __uint_as_float(hi);
    g_w1hi[i] = hif;
    g_w1lo[i] = __uint_as_float(cvt_tf32(w - hif));
}

// ---------------- GEMM1: h1 = x @ W1  via 3xTF32 mma, double-buffered -------
#define KC 32
#define GROWS 64
#define XSTR 36
#define WSTR 24
#define NCHUNK (F_IN / KC)

__global__ __launch_bounds__(128) void k_gemm1(const float* __restrict__ x, int N) {
    __shared__ float xs[2][GROWS * XSTR];
    __shared__ float wh[2][KC * WSTR];
    __shared__ float wl[2][KC * WSTR];
    const int tid = threadIdx.x;
    const int lane = tid & 31, w = tid >> 5;
    const int row0 = blockIdx.x * GROWS;
    const int wrow = w * 16;
    const int tr = lane >> 2, tc = lane & 3;
    const int wr = tid >> 2, wq = tid & 3;

    float d[2][4] = {{0.f, 0.f, 0.f, 0.f}, {0.f, 0.f, 0.f, 0.f}};

    int lr[4], lq = tid & 7;
#pragma unroll
    for (int i = 0; i < 4; i++) {
        int idx = tid + 128 * i;
        lr[i] = idx >> 3;
    }

    // prefetch chunk 0 -> buffer 0
#pragma unroll
    for (int i = 0; i < 4; i++) {
        int gr = row0 + lr[i]; if (gr >= N) gr = N - 1;
        cp_async16(xs[0] + lr[i] * XSTR + lq * 4, x + (size_t)gr * F_IN + lq * 4);
    }
    cp_async16(wh[0] + wr * WSTR + wq * 4, g_w1hi + wr * HID + wq * 4);
    cp_async16(wl[0] + wr * WSTR + wq * 4, g_w1lo + wr * HID + wq * 4);
    cp_commit();

    for (int ch = 0; ch < NCHUNK; ch++) {
        const int b = ch & 1;
        if (ch + 1 < NCHUNK) {
            int kc = (ch + 1) * KC;
#pragma unroll
            for (int i = 0; i < 4; i++) {
                int gr = row0 + lr[i]; if (gr >= N) gr = N - 1;
                cp_async16(xs[b ^ 1] + lr[i] * XSTR + lq * 4,
                           x + (size_t)gr * F_IN + kc + lq * 4);
            }
            cp_async16(wh[b ^ 1] + wr * WSTR + wq * 4, g_w1hi + (kc + wr) * HID + wq * 4);
            cp_async16(wl[b ^ 1] + wr * WSTR + wq * 4, g_w1lo + (kc + wr) * HID + wq * 4);
            cp_commit();
            cp_wait<1>();
        } else {
            cp_wait<0>();
        }
        __syncthreads();

        const float* xb = xs[b];
        const float* whb = wh[b];
        const float* wlb = wl[b];
#pragma unroll
        for (int ks = 0; ks < KC / 8; ks++) {
            int kb = ks * 8;
            float a_f[4];
            a_f[0] = xb[(wrow + tr) * XSTR + kb + tc];
            a_f[1] = xb[(wrow + tr + 8) * XSTR + kb + tc];
            a_f[2] = xb[(wrow + tr) * XSTR + kb + tc + 4];
            a_f[3] = xb[(wrow + tr + 8) * XSTR + kb + tc + 4];
            unsigned ah[4], al[4];
#pragma unroll
            for (int j = 0; j < 4; j++) {
                ah[j] = cvt_tf32(a_f[j]);
                al[j] = cvt_tf32(a_f[j] - __uint_as_float(ah[j]));
            }
#pragma unroll
            for (int nt = 0; nt < 2; nt++) {
                int b0i = (kb + tc) * WSTR + nt * 8 + tr;
                int b1i = b0i + 4 * WSTR;
                unsigned bh0 = __float_as_uint(whb[b0i]);
                unsigned bh1 = __float_as_uint(whb[b1i]);
                unsigned bl0 = __float_as_uint(wlb[b0i]);
                unsigned bl1 = __float_as_uint(wlb[b1i]);
                mma_tf32(d[nt], ah, bh0, bh1);
                mma_tf32(d[nt], al, bh0, bh1);
                mma_tf32(d[nt], ah, bl0, bl1);
            }
        }
        __syncthreads();
    }

    int r0 = row0 + wrow + tr, r1 = r0 + 8;
#pragma unroll
    for (int nt = 0; nt < 2; nt++) {
        int c = nt * 8 + 2 * tc;
        if (r0 < N)
            *(float2*)(g_h1 + (size_t)r0 * HID + c) = make_float2(d[nt][0], d[nt][1]);
        if (r1 < N)
            *(float2*)(g_h1 + (size_t)r1 * HID + c) = make_float2(d[nt][2], d[nt][3]);
    }
}

// ---------------- scan pass 1 ----------------
__global__ __launch_bounds__(512) void k_scan1(int N) {
    __shared__ int wsum[16];
    const int t = threadIdx.x;
    const int base = blockIdx.x * SCAN_CH + t * 4;
    int v0 = (base + 0 < N) ? g_degcnt[base + 0] : 0;
    int v1 = (base + 1 < N) ? g_degcnt[base + 1] : 0;
    int v2 = (base + 2 < N) ? g_degcnt[base + 2] : 0;
    int v3 = (base + 3 < N) ? g_degcnt[base + 3] : 0;
    int s1 = v0 + v1, s2 = s1 + v2, s3 = s2 + v3;
    int tot = s3;

    int lane = t & 31, w = t >> 5;
    int sc = tot;
#pragma unroll
    for (int d = 1; d < 32; d <<= 1) {
        int u = __shfl_up_sync(0xffffffffu, sc, d);
        if (lane >= d) sc += u;
    }
    if (lane == 31) wsum[w] = sc;
    __syncthreads();
    if (w == 0) {
        int xv = (lane < 16) ? wsum[lane] : 0;
#pragma unroll
        for (int d = 1; d < 16; d <<= 1) {
            int u = __shfl_up_sync(0xffffffffu, xv, d);
            if (lane >= d) xv += u;
        }
        if (lane < 16) wsum[lane] = xv;
    }
    __syncthreads();
    int woff = (w > 0) ? wsum[w - 1] : 0;
    int excl = woff + sc - tot;
    if (base + 0 < N) g_incl[base + 0] = excl + v0;
    if (base + 1 < N) g_incl[base + 1] = excl + s1;
    if (base + 2 < N) g_incl[base + 2] = excl + s2;
    if (base + 3 < N) g_incl[base + 3] = excl + s3;
    if (t == 0) g_bsum[blockIdx.x] = wsum[15];
}

// ---------------- scan pass 2: warp-scan of block sums ----------------
__global__ void k_scan2(int NB) {
    __shared__ int ws[8];
    int t = threadIdx.x;
    int lane = t & 31, w = t >> 5;
    int v = (t < NB) ? g_bsum[t] : 0;
    int s = v;
#pragma unroll
    for (int d = 1; d < 32; d <<= 1) {
        int u = __shfl_up_sync(0xffffffffu, s, d);
        if (lane >= d) s += u;
    }
    if (lane == 31) ws[w] = s;
    __syncthreads();
    if (w == 0 && lane < 8) {
        int xv = ws[lane];
#pragma unroll
        for (int d = 1; d < 8; d <<= 1) {
            int u = __shfl_up_sync(0xffu, xv, d);
            if (lane >= d) xv += u;
        }
        ws[lane] = xv;
    }
    __syncthreads();
    int off = (w > 0) ? ws[w - 1] : 0;
    if (t < NB) g_boff[t] = off + s - v;   // exclusive
}

// ---------------- scan pass 3 ----------------
__global__ void k_scan3(int N, int E) {
    int i = blockIdx.x * blockDim.x + threadIdx.x;
    if (i >= N) return;
    int deg = g_degcnt[i];
    int off = g_boff[i / SCAN_CH] + g_incl[i] - deg;
    g_off[i] = off;
    g_cur[i] = off;
    g_dinv[i] = rsqrtf((float)(deg + 1));
    if (i == 0) g_off[N] = E;
}

// ---------------- fill CSR edge list (packed src + dinv[src]) ----------------
__global__ void k_fill(const int* __restrict__ src,
                       const int* __restrict__ dst, int E) {
    int e = blockIdx.x * blockDim.x + threadIdx.x;
    if (e >= E) return;
    int d = dst[e];
    int s = src[e];
    int slot = atomicAdd(&g_cur[d], 1);
    g_epack[slot] = make_int2(s, __float_as_int(g_dinv[s]));
}

// ---------------- gather layer 1 (warp per node) + relu + W2 -> h2 ----------
__global__ __launch_bounds__(128) void k_gather1(const float* __restrict__ b1,
                                                 const float* __restrict__ W2, int N) {
    const int warp = (blockIdx.x * blockDim.x + threadIdx.x) >> 5;
    const int lane = threadIdx.x & 31;
    if (warp >= N) return;
    const int i = warp;
    const int eg = lane >> 2, p = lane & 3;

    const int beg = g_off[i], end = g_off[i + 1];
    const float di = g_dinv[i];

    float4 acc = make_float4(0.f, 0.f, 0.f, 0.f);
#pragma unroll 2
    for (int c = beg + eg; c < end; c += 8) {
        int2 pk = g_epack[c];
        float ds = __int_as_float(pk.y);
        float4 h = *(const float4*)(g_h1 + (size_t)pk.x * HID + p * 4);
        acc.x = fmaf(ds, h.x, acc.x);
        acc.y = fmaf(ds, h.y, acc.y);
        acc.z = fmaf(ds, h.z, acc.z);
        acc.w = fmaf(ds, h.w, acc.w);
    }
#pragma unroll
    for (int d = 16; d >= 4; d >>= 1) {
        acc.x += __shfl_xor_sync(0xffffffffu, acc.x, d);
        acc.y += __shfl_xor_sync(0xffffffffu, acc.y, d);
        acc.z += __shfl_xor_sync(0xffffffffu, acc.z, d);
        acc.w += __shfl_xor_sync(0xffffffffu, acc.w, d);
    }

    float o0 = 0.f, o1 = 0.f;
    {
        float4 hs = *(const float4*)(g_h1 + (size_t)i * HID + p * 4);
        float4 bb = __ldg((const float4*)(b1 + p * 4));
        float d2 = di * di;
        float t0 = fmaxf(acc.x * di + d2 * hs.x + bb.x, 0.f);
        float t1 = fmaxf(acc.y * di + d2 * hs.y + bb.y, 0.f);
        float t2 = fmaxf(acc.z * di + d2 * hs.z + bb.z, 0.f);
        float t3 = fmaxf(acc.w * di + d2 * hs.w + bb.w, 0.f);
        int c = p * 4;
        o0 = t0 * __ldg(W2 + (c + 0) * NCLS + 0) + t1 * __ldg(W2 + (c + 1) * NCLS + 0)
           + t2 * __ldg(W2 + (c + 2) * NCLS + 0) + t3 * __ldg(W2 + (c + 3) * NCLS + 0);
        o1 = t0 * __ldg(W2 + (c + 0) * NCLS + 1) + t1 * __ldg(W2 + (c + 1) * NCLS + 1)
           + t2 * __ldg(W2 + (c + 2) * NCLS + 1) + t3 * __ldg(W2 + (c + 3) * NCLS + 1);
    }
    o0 += __shfl_xor_sync(0xffffffffu, o0, 2);
    o1 += __shfl_xor_sync(0xffffffffu, o1, 2);
    o0 += __shfl_xor_sync(0xffffffffu, o0, 1);
    o1 += __shfl_xor_sync(0xffffffffu, o1, 1);
    if (lane == 0)
        *(float2*)(g_h2 + (size_t)i * NCLS) = make_float2(o0, o1);
}

// ---------------- gather layer 2 (warp per node) + log_softmax -> out -------
__global__ __launch_bounds__(128) void k_gather2(const float* __restrict__ b2,
                                                 float* __restrict__ out, int N) {
    const int warp = (blockIdx.x * blockDim.x + threadIdx.x) >> 5;
    const int lane = threadIdx.x & 31;
    if (warp >= N) return;
    const int i = warp;
    const int beg = g_off[i], end = g_off[i + 1];
    const float di = g_dinv[i];

    float a0 = 0.f, a1 = 0.f;
#pragma unroll 2
    for (int c = beg + lane; c < end; c += 32) {
        int2 pk = g_epack[c];
        float ds = __int_as_float(pk.y);
        float2 h = *(const float2*)(g_h2 + (size_t)pk.x * NCLS);
        a0 = fmaf(ds, h.x, a0);
        a1 = fmaf(ds, h.y, a1);
    }
#pragma unroll
    for (int d = 16; d >= 1; d >>= 1) {
        a0 += __shfl_xor_sync(0xffffffffu, a0, d);
        a1 += __shfl_xor_sync(0xffffffffu, a1, d);
    }
    if (lane == 0) {
        float d2 = di * di;
        float2 hs = *(const float2*)(g_h2 + (size_t)i * NCLS);
        float v0 = a0 * di + d2 * hs.x + __ldg(b2 + 0);
        float v1 = a1 * di + d2 * hs.y + __ldg(b2 + 1);
        float m = fmaxf(v0, v1);
        float lse = m + logf(expf(v0 - m) + expf(v1 - m));
        *(float2*)(out + (size_t)i * NCLS) = make_float2(v0 - lse, v1 - lse);
    }
}

// ---------------------------------------------------------------------------
extern "C" void kernel_launch(void* const* d_in, const int* in_sizes, int n_in,
                              void* d_out, int out_size) {
    const float* x = (const float*)d_in[0];
    const int* ei = (const int*)d_in[1];
    const float* W1 = (const float*)d_in[2];
    const float* b1 = (const float*)d_in[3];
    const float* W2 = (const float*)d_in[4];
    const float* b2 = (const float*)d_in[5];
    float* out = (float*)d_out;

    const int N = in_sizes[0] / F_IN;
    const int E = in_sizes[1] / 2;
    const int* src = ei;
    const int* dst = ei + E;
    const int NB = (N + SCAN_CH - 1) / SCAN_CH;

    // Fork a side stream so GEMM (DRAM-bound) overlaps CSR build (L2-bound).
    // Created per call; kernel_launch runs only a handful of times, and
    // streams/events hold no tracked device memory.
    cudaStream_t s2;
    cudaEvent_t evFork, evJoin;
    cudaStreamCreateWithFlags(&s2, cudaStreamNonBlocking);
    cudaEventCreateWithFlags(&evFork, cudaEventDisableTiming);
    cudaEventCreateWithFlags(&evJoin, cudaEventDisableTiming);

    cudaEventRecord(evFork, 0);
    cudaStreamWaitEvent(s2, evFork, 0);

    // branch A (s2): GEMM path
    k_wsplit<<<(F_IN * HID + 255) / 256, 256, 0, s2>>>(W1);
    k_gemm1<<<(N + GROWS - 1) / GROWS, 128, 0, s2>>>(x, N);
    cudaEventRecord(evJoin, s2);

    // branch B (main): CSR build
    k_zero<<<(N + 255) / 256, 256>>>(N);
    k_deg<<<(E / 4 + 255) / 256, 256>>>(dst, E);
    k_scan1<<<NB, 512>>>(N);
    k_scan2<<<1, 256>>>(NB);
    k_scan3<<<(N + 255) / 256, 256>>>(N, E);
    k_fill<<<(E + 511) / 512, 512>>>(src, dst, E);

    // join, then gathers
    cudaStreamWaitEvent(0, evJoin, 0);
    k_gather1<<<(N * 32 + 127) / 128, 128>>>(b1, W2, N);
    k_gather2<<<(N * 32 + 127) / 128, 128>>>(b2, out, N);
    // no destroy: objects must outlive capture; leak is bounded (<=3 calls)
}